// round 3
// baseline (speedup 1.0000x reference)
#include <cuda_runtime.h>

#define LOG2E 1.4426950408889634f
#define BLK 128
#define RPB 256   // rows per block = 2 per thread

typedef unsigned long long u64;

__device__ __forceinline__ float ex2f(float x){ float y; asm("ex2.approx.f32 %0, %1;" : "=f"(y) : "f"(x)); return y; }
__device__ __forceinline__ float rcpf(float x){ float y; asm("rcp.approx.f32 %0, %1;" : "=f"(y) : "f"(x)); return y; }
__device__ __forceinline__ u64 pk(float lo, float hi){ u64 r; asm("mov.b64 %0, {%1,%2};" : "=l"(r) : "f"(lo), "f"(hi)); return r; }
__device__ __forceinline__ void unpk(u64 v, float& lo, float& hi){ asm("mov.b64 {%0,%1}, %2;" : "=f"(lo), "=f"(hi) : "l"(v)); }
__device__ __forceinline__ u64 f2fma(u64 a,u64 b,u64 c){ u64 d; asm("fma.rn.f32x2 %0, %1, %2, %3;" : "=l"(d) : "l"(a),"l"(b),"l"(c)); return d; }
__device__ __forceinline__ u64 f2add(u64 a,u64 b){ u64 d; asm("add.rn.f32x2 %0, %1, %2;" : "=l"(d) : "l"(a),"l"(b)); return d; }
__device__ __forceinline__ u64 f2mul(u64 a,u64 b){ u64 d; asm("mul.rn.f32x2 %0, %1, %2;" : "=l"(d) : "l"(a),"l"(b)); return d; }
__device__ __forceinline__ u64 f2ex2(u64 v){ float lo,hi; unpk(v,lo,hi); return pk(ex2f(lo), ex2f(hi)); }
__device__ __forceinline__ u64 f2rcp(u64 v){ float lo,hi; unpk(v,lo,hi); return pk(rcpf(lo), rcpf(hi)); }

__global__ __launch_bounds__(BLK)
void logic_kernel(const float* __restrict__ state,
                  const float* __restrict__ c_templates,
                  const float* __restrict__ c_gammas,
                  const float* __restrict__ a_templates,
                  const float* __restrict__ a_gammas,
                  const float* __restrict__ a_body_W,
                  const float* __restrict__ a_body_b,
                  const float* __restrict__ a_head_W,
                  const float* __restrict__ a_head_b,
                  const float* __restrict__ act_W,
                  const float* __restrict__ act_b,
                  float* __restrict__ out, int B)
{
    // ---- weights in shared as duplicated (x,x) u64 pairs: one LDS.64 feeds a packed op ----
    __shared__ u64 s_nt0[12], s_nt1[12], s_nw0[12], s_nw1[12];     // layer1: -templ, -(1-g)*log2e
    __shared__ u64 s_K[12], s_u0[12], s_u1[12], s_m0[12], s_m1[12];// layer2 quadratic consts
    __shared__ u64 s_bW[96], s_hW[48], s_hb[12], s_aWt[108], s_ab[9];
    __shared__ u64 s_io[(RPB/2) * 19];   // pair-packed input staging; reused for output

    const int t = threadIdx.x;

    if (t < 12) {
        // layer1 consts (rule t)
        float t0 = c_templates[2*t], t1 = c_templates[2*t+1];
        float w0 = (1.0f - __saturatef(c_gammas[2*t]))   * LOG2E;
        float w1 = (1.0f - __saturatef(c_gammas[2*t+1])) * LOG2E;
        s_nt0[t] = pk(-t0, -t0);  s_nt1[t] = pk(-t1, -t1);
        s_nw0[t] = pk(-w0, -w0);  s_nw1[t] = pk(-w1, -w1);
        // layer2 consts (group t): m_neg = K + u0*x + u1*y - w0*x^2 - w1*y^2
        float a0 = a_templates[2*t], a1 = a_templates[2*t+1];
        float v0 = (1.0f - __saturatef(a_gammas[2*t]))   * LOG2E;
        float v1 = (1.0f - __saturatef(a_gammas[2*t+1])) * LOG2E;
        float K  = -(v0*a0*a0 + v1*a1*a1);
        float u0 = 2.0f*v0*a0, u1 = 2.0f*v1*a1;
        s_K[t]  = pk(K, K);   s_u0[t] = pk(u0, u0); s_u1[t] = pk(u1, u1);
        s_m0[t] = pk(-v0,-v0); s_m1[t] = pk(-v1,-v1);
        float hb = a_head_b[t];  s_hb[t] = pk(hb, hb);
    }
    if (t < 96) { float v = a_body_W[t]; s_bW[t] = pk(v, v); }
    if (t < 48) { float v = a_head_W[t]; s_hW[t] = pk(v, v); }
    if (t < 108){ float v = act_W[t];    s_aWt[t] = pk(v, v); }
    if (t < 9)  { float v = act_b[t];    s_ab[t]  = pk(v, v); }
    // (a_body_b folded below via s_bb)
    __shared__ u64 s_bb[48];
    if (t < 48) { float v = a_body_b[t]; s_bb[t] = pk(v, v); }

    // ---- coalesced input staging: 256 rows x 18 floats -> pair-packed layout ----
    // float view: element (pair, c, half) at [(pair*19 + c)*2 + half]
    float* s_f = (float*)s_io;
    const long long in_base = (long long)blockIdx.x * (RPB * 18);
    const long long in_lim  = (long long)B * 18;
    for (int k = t; k < RPB * 18; k += BLK) {
        long long g = in_base + k;
        float v = (g < in_lim) ? __ldg(&state[g]) : 0.0f;
        int rowl = k / 18, c = k % 18;
        s_f[((rowl >> 1) * 19 + c) * 2 + (rowl & 1)] = v;
    }
    __syncthreads();

    // ---- per-thread pair load: u64 = {row 2t, row 2t+1} for each feature ----
    u64 b0p[9], b1p[9];
    {
        const u64* my = &s_io[t * 19];
        #pragma unroll
        for (int i = 0; i < 9; i++) { b0p[i] = my[2*i]; b1p[i] = my[2*i+1]; }
    }

    // ---- ConcreteLayer: 12 rules, shift-free softmax over 9 ----
    u64 cf0p[12], cf1p[12];
    #pragma unroll
    for (int r = 0; r < 12; r++) {
        const u64 nt0 = s_nt0[r], nt1 = s_nt1[r], nw0 = s_nw0[r], nw1 = s_nw1[r];
        u64 sum = 0ull, wsum = 0ull;       // +0.0f in both halves
        float emlo = 0.0f, emhi = 0.0f;
        #pragma unroll
        for (int i = 0; i < 9; i++) {
            u64 d0 = f2add(b0p[i], nt0);            // (b - t): sign-free under squaring
            u64 d1 = f2add(b1p[i], nt1);
            u64 m  = f2mul(f2mul(nw0, d0), d0);     // m_neg = -(w0 d0^2 + w1 d1^2) [log2 domain]
            m = f2fma(f2mul(nw1, d1), d1, m);
            float mlo, mhi; unpk(m, mlo, mhi);
            float elo = ex2f(mlo), ehi = ex2f(mhi); // e = exp(-ms)
            emlo = fmaxf(emlo, elo); emhi = fmaxf(emhi, ehi);
            u64 e = pk(elo, ehi);
            sum  = f2add(sum, e);
            wsum = f2fma(e, b1p[i], wsum);
        }
        cf0p[r] = pk(emlo, emhi);                   // exp(-min ms) = max e
        cf1p[r] = f2mul(wsum, f2rcp(sum));          // matched[...,1]
    }

    // ---- squares for layer-2 quadratic form ----
    u64 cf0sq[12], cf1sq[12];
    #pragma unroll
    for (int i = 0; i < 12; i++) { cf0sq[i] = f2mul(cf0p[i], cf0p[i]); cf1sq[i] = f2mul(cf1p[i], cf1p[i]); }

    // ---- action accumulators init with bias; updated as each concept is produced ----
    u64 qp[9];
    #pragma unroll
    for (int k = 0; k < 9; k++) qp[k] = s_ab[k];

    // ---- AbstractionLayer: 6 rules x 2 clauses, shift-free softmax over 12 ----
    #pragma unroll
    for (int r = 0; r < 6; r++) {
        u64 cap[4];
        #pragma unroll
        for (int j = 0; j < 2; j++) {
            const int g = r*2 + j;
            const u64 K = s_K[g], u0 = s_u0[g], u1 = s_u1[g], m0 = s_m0[g], m1 = s_m1[g];
            u64 sum = 0ull, sl0 = 0ull, sl1 = 0ull;
            #pragma unroll
            for (int i = 0; i < 12; i++) {
                u64 m = f2fma(u0, cf0p[i], K);
                m = f2fma(u1, cf1p[i], m);
                m = f2fma(m0, cf0sq[i], m);
                m = f2fma(m1, cf1sq[i], m);
                u64 e = f2ex2(m);
                sum = f2add(sum, e);
                sl0 = f2fma(e, cf0p[i], sl0);
                sl1 = f2fma(e, cf1p[i], sl1);
            }
            u64 inv  = f2rcp(sum);
            u64 sel0 = f2mul(sl0, inv);
            u64 sel1 = f2mul(sl1, inv);
            #pragma unroll
            for (int v = 0; v < 4; v++) {
                u64 val = f2fma(s_bW[(g*4+v)*2 + 0], sel0,
                          f2fma(s_bW[(g*4+v)*2 + 1], sel1, s_bb[g*4+v]));
                cap[v] = (j == 0) ? val : f2add(cap[v], val);
            }
        }
        #pragma unroll
        for (int l = 0; l < 2; l++) {
            const int m = r*2 + l;
            u64 c = s_hb[m];
            #pragma unroll
            for (int v = 0; v < 4; v++) c = f2fma(cap[v], s_hW[m*4 + v], c);
            // fold concept m straight into all 9 q-values
            #pragma unroll
            for (int k = 0; k < 9; k++) qp[k] = f2fma(s_aWt[k*12 + m], c, qp[k]);
        }
    }

    // ---- output staging (reuse s_io as float buffer) + coalesced store ----
    __syncthreads();
    #pragma unroll
    for (int k = 0; k < 9; k++) {
        float lo, hi; unpk(qp[k], lo, hi);
        s_f[(2*t)   * 9 + k] = lo;
        s_f[(2*t+1) * 9 + k] = hi;
    }
    __syncthreads();
    const long long out_base = (long long)blockIdx.x * (RPB * 9);
    const long long out_lim  = (long long)B * 9;
    for (int k = t; k < RPB * 9; k += BLK) {
        long long g = out_base + k;
        if (g < out_lim) out[g] = s_f[k];
    }
}

extern "C" void kernel_launch(void* const* d_in, const int* in_sizes, int n_in,
                              void* d_out, int out_size) {
    const float* state       = (const float*)d_in[0];
    const float* c_templates = (const float*)d_in[1];
    const float* c_gammas    = (const float*)d_in[2];
    const float* a_templates = (const float*)d_in[3];
    const float* a_gammas    = (const float*)d_in[4];
    const float* a_body_W    = (const float*)d_in[5];
    const float* a_body_b    = (const float*)d_in[6];
    const float* a_head_W    = (const float*)d_in[7];
    const float* a_head_b    = (const float*)d_in[8];
    const float* act_W       = (const float*)d_in[9];
    const float* act_b       = (const float*)d_in[10];
    float* out = (float*)d_out;

    const int B = in_sizes[0] / 18;
    const int grid = (B + RPB - 1) / RPB;
    logic_kernel<<<grid, BLK>>>(state, c_templates, c_gammas, a_templates,
                                a_gammas, a_body_W, a_body_b, a_head_W,
                                a_head_b, act_W, act_b, out, B);
}

// round 4
// speedup vs baseline: 1.0458x; 1.0458x over previous
#include <cuda_runtime.h>

#define LOG2E 1.4426950408889634f
#define BLK 128
#define RPB 256   // rows per block = 2 per thread

typedef unsigned long long u64;

__device__ __forceinline__ float ex2f(float x){ float y; asm("ex2.approx.f32 %0, %1;" : "=f"(y) : "f"(x)); return y; }
__device__ __forceinline__ float rcpf(float x){ float y; asm("rcp.approx.f32 %0, %1;" : "=f"(y) : "f"(x)); return y; }
__device__ __forceinline__ u64 pk(float lo, float hi){ u64 r; asm("mov.b64 %0, {%1,%2};" : "=l"(r) : "f"(lo), "f"(hi)); return r; }
__device__ __forceinline__ void unpk(u64 v, float& lo, float& hi){ asm("mov.b64 {%0,%1}, %2;" : "=f"(lo), "=f"(hi) : "l"(v)); }
__device__ __forceinline__ u64 f2fma(u64 a,u64 b,u64 c){ u64 d; asm("fma.rn.f32x2 %0, %1, %2, %3;" : "=l"(d) : "l"(a),"l"(b),"l"(c)); return d; }
__device__ __forceinline__ u64 f2add(u64 a,u64 b){ u64 d; asm("add.rn.f32x2 %0, %1, %2;" : "=l"(d) : "l"(a),"l"(b)); return d; }
__device__ __forceinline__ u64 f2mul(u64 a,u64 b){ u64 d; asm("mul.rn.f32x2 %0, %1, %2;" : "=l"(d) : "l"(a),"l"(b)); return d; }
__device__ __forceinline__ u64 f2ex2(u64 v){ float lo,hi; unpk(v,lo,hi); return pk(ex2f(lo), ex2f(hi)); }
__device__ __forceinline__ u64 f2rcp(u64 v){ float lo,hi; unpk(v,lo,hi); return pk(rcpf(lo), rcpf(hi)); }

__global__ __launch_bounds__(BLK, 4)
void logic_kernel(const float* __restrict__ state,
                  const float* __restrict__ c_templates,
                  const float* __restrict__ c_gammas,
                  const float* __restrict__ a_templates,
                  const float* __restrict__ a_gammas,
                  const float* __restrict__ a_body_W,
                  const float* __restrict__ a_body_b,
                  const float* __restrict__ a_head_W,
                  const float* __restrict__ a_head_b,
                  const float* __restrict__ act_W,
                  const float* __restrict__ act_b,
                  float* __restrict__ out, int B)
{
    // ---- weights in shared as duplicated (x,x) u64 pairs ----
    // layer1 hybrid: x diff-form, y expanded.  m_neg = Ky + u1*b1 + n1*b1^2 + (n0*d0)*d0, d0=b0-t0
    __shared__ u64 s1_nt0[12], s1_n0[12], s1_Ky[12], s1_u1[12], s1_n1[12];
    // layer2 hybrid: x expanded, y diff-form.  m_neg = Kx + u0*x + n0*x^2 + (n1*d1)*d1, d1=y-a1
    __shared__ u64 s2_Kx[12], s2_u0[12], s2_n0[12], s2_na1[12], s2_n1[12];
    __shared__ u64 s_bW[96], s_bb[48], s_hW[48], s_hb[12], s_aWt[108], s_ab[9];
    __shared__ u64 s_io[(RPB/2) * 19];   // pair-packed input staging; reused for output

    const int t = threadIdx.x;

    if (t < 12) {
        // layer1 consts (rule t)
        float t0 = c_templates[2*t], t1 = c_templates[2*t+1];
        float w0 = (1.0f - __saturatef(c_gammas[2*t]))   * LOG2E;
        float w1 = (1.0f - __saturatef(c_gammas[2*t+1])) * LOG2E;
        s1_nt0[t] = pk(-t0, -t0);
        s1_n0[t]  = pk(-w0, -w0);
        float Ky = -w1 * t1 * t1;
        float u1 = 2.0f * w1 * t1;
        s1_Ky[t] = pk(Ky, Ky);  s1_u1[t] = pk(u1, u1);  s1_n1[t] = pk(-w1, -w1);
        // layer2 consts (group t)
        float a0 = a_templates[2*t], a1 = a_templates[2*t+1];
        float v0 = (1.0f - __saturatef(a_gammas[2*t]))   * LOG2E;
        float v1 = (1.0f - __saturatef(a_gammas[2*t+1])) * LOG2E;
        float Kx = -v0 * a0 * a0;
        float u0 = 2.0f * v0 * a0;
        s2_Kx[t] = pk(Kx, Kx);  s2_u0[t] = pk(u0, u0);  s2_n0[t] = pk(-v0, -v0);
        s2_na1[t] = pk(-a1, -a1);  s2_n1[t] = pk(-v1, -v1);
        float hb = a_head_b[t];  s_hb[t] = pk(hb, hb);
    }
    if (t < 96) { float v = a_body_W[t]; s_bW[t] = pk(v, v); }
    if (t < 48) { float v = a_body_b[t]; s_bb[t] = pk(v, v);
                  float w = a_head_W[t]; s_hW[t] = pk(w, w); }
    if (t < 108){ float v = act_W[t];    s_aWt[t] = pk(v, v); }
    if (t < 9)  { float v = act_b[t];    s_ab[t]  = pk(v, v); }

    // ---- coalesced input staging: 256 rows x 18 floats -> pair-packed layout ----
    float* s_f = (float*)s_io;
    const long long in_base = (long long)blockIdx.x * (RPB * 18);
    const long long in_lim  = (long long)B * 18;
    for (int k = t; k < RPB * 18; k += BLK) {
        long long g = in_base + k;
        float v = (g < in_lim) ? __ldg(&state[g]) : 0.0f;
        int rowl = k / 18, c = k % 18;
        s_f[((rowl >> 1) * 19 + c) * 2 + (rowl & 1)] = v;
    }
    __syncthreads();

    // ---- per-thread pair load + y-squares ----
    u64 b0p[9], b1p[9], b1sq[9];
    {
        const u64* my = &s_io[t * 19];
        #pragma unroll
        for (int i = 0; i < 9; i++) {
            b0p[i] = my[2*i]; b1p[i] = my[2*i+1];
            b1sq[i] = f2mul(b1p[i], b1p[i]);
        }
    }

    // ---- ConcreteLayer: 12 rules, shift-free softmax over 9 ----
    u64 cf0p[12], cf1p[12];
    #pragma unroll
    for (int r = 0; r < 12; r++) {
        const u64 nt0 = s1_nt0[r], n0 = s1_n0[r];
        const u64 Ky = s1_Ky[r], u1 = s1_u1[r], n1 = s1_n1[r];
        u64 sum = 0ull, wsum = 0ull;
        float emlo = 0.0f, emhi = 0.0f;
        #pragma unroll
        for (int i = 0; i < 9; i++) {
            u64 m = f2fma(u1, b1p[i], Ky);
            m = f2fma(n1, b1sq[i], m);
            u64 d0 = f2add(b0p[i], nt0);
            m = f2fma(f2mul(n0, d0), d0, m);        // m_neg [log2 domain]
            float mlo, mhi; unpk(m, mlo, mhi);
            float elo = ex2f(mlo), ehi = ex2f(mhi); // e = exp(-ms)
            emlo = fmaxf(emlo, elo); emhi = fmaxf(emhi, ehi);
            u64 e = pk(elo, ehi);
            sum  = f2add(sum, e);
            wsum = f2fma(e, b1p[i], wsum);
        }
        cf0p[r] = pk(emlo, emhi);                   // exp(-min ms) = max e
        cf1p[r] = f2mul(wsum, f2rcp(sum));          // matched[...,1]
    }

    // ---- x-squares for layer-2 ----
    u64 cf0sq[12];
    #pragma unroll
    for (int i = 0; i < 12; i++) cf0sq[i] = f2mul(cf0p[i], cf0p[i]);

    // ---- action accumulators init with bias ----
    u64 qp[9];
    #pragma unroll
    for (int k = 0; k < 9; k++) qp[k] = s_ab[k];

    // ---- AbstractionLayer: 6 rules x 2 clauses, shift-free softmax over 12 ----
    #pragma unroll
    for (int r = 0; r < 6; r++) {
        u64 cap[4];
        #pragma unroll
        for (int j = 0; j < 2; j++) {
            const int g = r*2 + j;
            const u64 Kx = s2_Kx[g], u0 = s2_u0[g], n0 = s2_n0[g];
            const u64 na1 = s2_na1[g], n1 = s2_n1[g];
            u64 sum = 0ull, sl0 = 0ull, sl1 = 0ull;
            #pragma unroll
            for (int i = 0; i < 12; i++) {
                u64 m = f2fma(u0, cf0p[i], Kx);
                m = f2fma(n0, cf0sq[i], m);
                u64 d1 = f2add(cf1p[i], na1);
                m = f2fma(f2mul(n1, d1), d1, m);
                u64 e = f2ex2(m);
                sum = f2add(sum, e);
                sl0 = f2fma(e, cf0p[i], sl0);
                sl1 = f2fma(e, cf1p[i], sl1);
            }
            u64 inv  = f2rcp(sum);
            u64 sel0 = f2mul(sl0, inv);
            u64 sel1 = f2mul(sl1, inv);
            #pragma unroll
            for (int v = 0; v < 4; v++) {
                u64 val = f2fma(s_bW[(g*4+v)*2 + 0], sel0,
                          f2fma(s_bW[(g*4+v)*2 + 1], sel1, s_bb[g*4+v]));
                cap[v] = (j == 0) ? val : f2add(cap[v], val);
            }
        }
        #pragma unroll
        for (int l = 0; l < 2; l++) {
            const int m = r*2 + l;
            u64 c = s_hb[m];
            #pragma unroll
            for (int v = 0; v < 4; v++) c = f2fma(cap[v], s_hW[m*4 + v], c);
            #pragma unroll
            for (int k = 0; k < 9; k++) qp[k] = f2fma(s_aWt[k*12 + m], c, qp[k]);
        }
    }

    // ---- output staging (reuse s_io) + coalesced store ----
    __syncthreads();
    #pragma unroll
    for (int k = 0; k < 9; k++) {
        float lo, hi; unpk(qp[k], lo, hi);
        s_f[(2*t)   * 9 + k] = lo;
        s_f[(2*t+1) * 9 + k] = hi;
    }
    __syncthreads();
    const long long out_base = (long long)blockIdx.x * (RPB * 9);
    const long long out_lim  = (long long)B * 9;
    for (int k = t; k < RPB * 9; k += BLK) {
        long long g = out_base + k;
        if (g < out_lim) out[g] = s_f[k];
    }
}

extern "C" void kernel_launch(void* const* d_in, const int* in_sizes, int n_in,
                              void* d_out, int out_size) {
    const float* state       = (const float*)d_in[0];
    const float* c_templates = (const float*)d_in[1];
    const float* c_gammas    = (const float*)d_in[2];
    const float* a_templates = (const float*)d_in[3];
    const float* a_gammas    = (const float*)d_in[4];
    const float* a_body_W    = (const float*)d_in[5];
    const float* a_body_b    = (const float*)d_in[6];
    const float* a_head_W    = (const float*)d_in[7];
    const float* a_head_b    = (const float*)d_in[8];
    const float* act_W       = (const float*)d_in[9];
    const float* act_b       = (const float*)d_in[10];
    float* out = (float*)d_out;

    const int B = in_sizes[0] / 18;
    const int grid = (B + RPB - 1) / RPB;
    logic_kernel<<<grid, BLK>>>(state, c_templates, c_gammas, a_templates,
                                a_gammas, a_body_W, a_body_b, a_head_W,
                                a_head_b, act_W, act_b, out, B);
}

// round 5
// speedup vs baseline: 1.0655x; 1.0188x over previous
#include <cuda_runtime.h>

#define LOG2E 1.4426950408889634f
#define BLK 128

__device__ __forceinline__ float ex2f(float x){ float y; asm("ex2.approx.f32 %0, %1;" : "=f"(y) : "f"(x)); return y; }
__device__ __forceinline__ float rcpf(float x){ float y; asm("rcp.approx.f32 %0, %1;" : "=f"(y) : "f"(x)); return y; }

__global__ __launch_bounds__(BLK)
void logic_kernel(const float* __restrict__ state,
                  const float* __restrict__ c_templates,
                  const float* __restrict__ c_gammas,
                  const float* __restrict__ a_templates,
                  const float* __restrict__ a_gammas,
                  const float* __restrict__ a_body_W,
                  const float* __restrict__ a_body_b,
                  const float* __restrict__ a_head_W,
                  const float* __restrict__ a_head_b,
                  const float* __restrict__ act_W,
                  const float* __restrict__ act_b,
                  float* __restrict__ out, int B)
{
    // Layer-1 consts per rule (expanded quadratic, log2 domain):
    //   m_neg = C1 + u0*x + n0*x^2 + u1*y + n1*y^2
    __shared__ float s1C[12], s1u0[12], s1n0[12], s1u1[12], s1n1[12];
    // Layer-2 consts per (rule,clause) group, same form over (cf0, cf1)
    __shared__ float s2C[12], s2p0[12], s2q0[12], s2p1[12], s2q1[12];
    // Collapsed linear path: q += M[g] @ sel  (M[g] is 9x2), plus bias vector qb[9]
    __shared__ float sM[12 * 18];
    __shared__ float s_qb[9];
    // input staging (stride 19, conflict-free); reused as output staging
    __shared__ float s_io[BLK * 19];

    const int t = threadIdx.x;

    if (t < 12) {
        // ---- layer-1 rule t ----
        float t0 = c_templates[2*t], t1 = c_templates[2*t+1];
        float w0 = (1.0f - __saturatef(c_gammas[2*t]))   * LOG2E;
        float w1 = (1.0f - __saturatef(c_gammas[2*t+1])) * LOG2E;
        s1C[t]  = -(w0*t0*t0 + w1*t1*t1);
        s1u0[t] = 2.0f*w0*t0;  s1n0[t] = -w0;
        s1u1[t] = 2.0f*w1*t1;  s1n1[t] = -w1;
        // ---- layer-2 group t ----
        float a0 = a_templates[2*t], a1 = a_templates[2*t+1];
        float v0 = (1.0f - __saturatef(a_gammas[2*t]))   * LOG2E;
        float v1 = (1.0f - __saturatef(a_gammas[2*t+1])) * LOG2E;
        s2C[t]  = -(v0*a0*a0 + v1*a1*a1);
        s2p0[t] = 2.0f*v0*a0;  s2q0[t] = -v0;
        s2p1[t] = 2.0f*v1*a1;  s2q1[t] = -v1;
    }
    // M[g][k][m] = sum_{l,v} act_W[k,2r+l] * head_W[r,l,v] * body_W[r,j,v,m],  g = 2r+j
    if (t < 108) {
        #pragma unroll
        for (int half = 0; half < 2; half++) {
            int e = t + half * 108;          // 216 entries
            int g = e / 18, km = e % 18;
            int k = km / 2, m = km % 2;
            int r = g / 2, j = g % 2;
            float s = 0.0f;
            #pragma unroll
            for (int l = 0; l < 2; l++) {
                float aw = act_W[k*12 + 2*r + l];
                #pragma unroll
                for (int v = 0; v < 4; v++)
                    s += aw * a_head_W[(r*2+l)*4 + v] * a_body_W[((r*2+j)*4 + v)*2 + m];
            }
            sM[g*18 + k*2 + m] = s;
        }
    }
    // qb[k] = act_b[k] + sum_m12 act_W[k,m12] * (head_b[m12] + sum_v head_W[m12,v]*(body_b[r,0,v]+body_b[r,1,v]))
    if (t < 9) {
        float s = act_b[t];
        #pragma unroll
        for (int m12 = 0; m12 < 12; m12++) {
            int r = m12 / 2;
            float cb = a_head_b[m12];
            #pragma unroll
            for (int v = 0; v < 4; v++)
                cb += a_head_W[m12*4 + v] * (a_body_b[(r*2+0)*4 + v] + a_body_b[(r*2+1)*4 + v]);
            s += act_W[t*12 + m12] * cb;
        }
        s_qb[t] = s;
    }

    // ---- coalesced input staging ----
    const long long in_base = (long long)blockIdx.x * (BLK * 18);
    const long long in_lim  = (long long)B * 18;
    #pragma unroll
    for (int k = t; k < BLK * 18; k += BLK) {
        long long g = in_base + k;
        s_io[(k/18)*19 + (k%18)] = (g < in_lim) ? state[g] : 0.0f;
    }
    __syncthreads();

    // ---- per-row load + squares ----
    float x[9], y[9], x2[9], y2[9];
    {
        const float* my = &s_io[t * 19];
        #pragma unroll
        for (int i = 0; i < 9; i++) {
            x[i] = my[2*i]; y[i] = my[2*i+1];
            x2[i] = x[i]*x[i]; y2[i] = y[i]*y[i];
        }
    }

    // ---- ConcreteLayer: 12 rules, single-pass shift-free softmax over 9 ----
    float cf0[12], cf1[12];
    #pragma unroll
    for (int r = 0; r < 12; r++) {
        const float C = s1C[r], u0 = s1u0[r], n0 = s1n0[r], u1 = s1u1[r], n1 = s1n1[r];
        float sum = 0.0f, wsum = 0.0f, em = 0.0f;
        #pragma unroll
        for (int i = 0; i < 9; i++) {
            float m = fmaf(u0, x[i], C);
            m = fmaf(n0, x2[i], m);
            m = fmaf(u1, y[i], m);
            m = fmaf(n1, y2[i], m);          // m = -ms * log2e
            float e = ex2f(m);               // e = exp(-ms)
            em = fmaxf(em, e);
            sum += e;
            wsum = fmaf(e, y[i], wsum);
        }
        cf0[r] = em;                         // exp(-min ms) = max e
        cf1[r] = wsum * rcpf(sum);           // matched[...,1]
    }

    // ---- squares for layer 2 ----
    float cq0[12], cq1[12];
    #pragma unroll
    for (int i = 0; i < 12; i++) { cq0[i] = cf0[i]*cf0[i]; cq1[i] = cf1[i]*cf1[i]; }

    // ---- q accumulators (biases pre-folded) ----
    float qp[9];
    #pragma unroll
    for (int k = 0; k < 9; k++) qp[k] = s_qb[k];

    // ---- AbstractionLayer: 12 groups, softmax over 12; collapsed linear tail ----
    #pragma unroll
    for (int g = 0; g < 12; g++) {
        const float C = s2C[g], p0 = s2p0[g], q0 = s2q0[g], p1 = s2p1[g], q1 = s2q1[g];
        float sum = 0.0f, s0 = 0.0f, s1 = 0.0f;
        #pragma unroll
        for (int i = 0; i < 12; i++) {
            float m = fmaf(p0, cf0[i], C);
            m = fmaf(q0, cq0[i], m);
            m = fmaf(p1, cf1[i], m);
            m = fmaf(q1, cq1[i], m);
            float e = ex2f(m);
            sum += e;
            s0 = fmaf(e, cf0[i], s0);
            s1 = fmaf(e, cf1[i], s1);
        }
        float inv  = rcpf(sum);
        float sel0 = s0 * inv;
        float sel1 = s1 * inv;
        const float* M = &sM[g * 18];
        #pragma unroll
        for (int k = 0; k < 9; k++) {
            qp[k] = fmaf(M[k*2 + 0], sel0, qp[k]);
            qp[k] = fmaf(M[k*2 + 1], sel1, qp[k]);
        }
    }

    // ---- output staging (reuse s_io) + coalesced store ----
    __syncthreads();
    #pragma unroll
    for (int k = 0; k < 9; k++) s_io[t*9 + k] = qp[k];
    __syncthreads();

    const long long out_base = (long long)blockIdx.x * (BLK * 9);
    const long long out_lim  = (long long)B * 9;
    #pragma unroll
    for (int k = t; k < BLK * 9; k += BLK) {
        long long g = out_base + k;
        if (g < out_lim) out[g] = s_io[k];
    }
}

extern "C" void kernel_launch(void* const* d_in, const int* in_sizes, int n_in,
                              void* d_out, int out_size) {
    const float* state       = (const float*)d_in[0];
    const float* c_templates = (const float*)d_in[1];
    const float* c_gammas    = (const float*)d_in[2];
    const float* a_templates = (const float*)d_in[3];
    const float* a_gammas    = (const float*)d_in[4];
    const float* a_body_W    = (const float*)d_in[5];
    const float* a_body_b    = (const float*)d_in[6];
    const float* a_head_W    = (const float*)d_in[7];
    const float* a_head_b    = (const float*)d_in[8];
    const float* act_W       = (const float*)d_in[9];
    const float* act_b       = (const float*)d_in[10];
    float* out = (float*)d_out;

    const int B = in_sizes[0] / 18;
    const int grid = (B + BLK - 1) / BLK;
    logic_kernel<<<grid, BLK>>>(state, c_templates, c_gammas, a_templates,
                                a_gammas, a_body_W, a_body_b, a_head_W,
                                a_head_b, act_W, act_b, out, B);
}

// round 6
// speedup vs baseline: 1.1558x; 1.0848x over previous
#include <cuda_runtime.h>

#define LOG2E 1.4426950408889634f
#define BLK 128

typedef unsigned long long u64;

__device__ __forceinline__ float ex2f(float x){ float y; asm("ex2.approx.f32 %0, %1;" : "=f"(y) : "f"(x)); return y; }
__device__ __forceinline__ float rcpf(float x){ float y; asm("rcp.approx.f32 %0, %1;" : "=f"(y) : "f"(x)); return y; }
__device__ __forceinline__ u64 pk(float lo, float hi){ u64 r; asm("mov.b64 %0, {%1,%2};" : "=l"(r) : "f"(lo), "f"(hi)); return r; }
__device__ __forceinline__ void unpk(u64 v, float& lo, float& hi){ asm("mov.b64 {%0,%1}, %2;" : "=f"(lo), "=f"(hi) : "l"(v)); }
__device__ __forceinline__ u64 f2fma(u64 a,u64 b,u64 c){ u64 d; asm("fma.rn.f32x2 %0, %1, %2, %3;" : "=l"(d) : "l"(a),"l"(b),"l"(c)); return d; }
__device__ __forceinline__ u64 f2add(u64 a,u64 b){ u64 d; asm("add.rn.f32x2 %0, %1, %2;" : "=l"(d) : "l"(a),"l"(b)); return d; }
__device__ __forceinline__ u64 f2mul(u64 a,u64 b){ u64 d; asm("mul.rn.f32x2 %0, %1, %2;" : "=l"(d) : "l"(a),"l"(b)); return d; }

__global__ __launch_bounds__(BLK, 5)
void logic_kernel(const float* __restrict__ state,
                  const float* __restrict__ c_templates,
                  const float* __restrict__ c_gammas,
                  const float* __restrict__ a_templates,
                  const float* __restrict__ a_gammas,
                  const float* __restrict__ a_body_W,
                  const float* __restrict__ a_body_b,
                  const float* __restrict__ a_head_W,
                  const float* __restrict__ a_head_b,
                  const float* __restrict__ act_W,
                  const float* __restrict__ act_b,
                  float* __restrict__ out, int B)
{
    // Layer-1 per rule (expanded quadratic, log2 dom): m = C + u0 x + n0 x^2 + u1 y + n1 y^2
    __shared__ float4 s1a[12];   // {C, u0, n0, u1}
    __shared__ float  s1b[12];   // n1
    // Layer-2 per group-PAIR (diff form), packed {g=2p | g=2p+1}:
    //   m = (n0*d0)*d0 + (n1*d1)*d1,  d0 = cf0 + nta0, d1 = cf1 + nta1
    __shared__ u64 s2[6][4];     // {nta0, n0, nta1, n1}
    // Collapsed tail: q += M[g] @ sel; M packed across the group pair
    __shared__ u64 sMp[6][18];   // [gpair][k*2+m] = {M[2p][k][m] | M[2p+1][k][m]}
    __shared__ float s_qb[9];
    __shared__ float s_io[BLK * 19];   // input staging; reused as output staging

    const int t = threadIdx.x;

    if (t < 12) {
        float t0 = c_templates[2*t], t1 = c_templates[2*t+1];
        float w0 = (1.0f - __saturatef(c_gammas[2*t]))   * LOG2E;
        float w1 = (1.0f - __saturatef(c_gammas[2*t+1])) * LOG2E;
        float4 a;
        a.x = -(w0*t0*t0 + w1*t1*t1);   // C
        a.y = 2.0f*w0*t0;               // u0
        a.z = -w0;                      // n0
        a.w = 2.0f*w1*t1;               // u1
        s1a[t] = a;
        s1b[t] = -w1;                   // n1
    }
    if (t < 6) {
        float lo[4], hi[4];
        #pragma unroll
        for (int h = 0; h < 2; h++) {
            int g = 2*t + h;
            float a0 = a_templates[2*g], a1 = a_templates[2*g+1];
            float v0 = (1.0f - __saturatef(a_gammas[2*g]))   * LOG2E;
            float v1 = (1.0f - __saturatef(a_gammas[2*g+1])) * LOG2E;
            float* d = h ? hi : lo;
            d[0] = -a0; d[1] = -v0; d[2] = -a1; d[3] = -v1;
        }
        #pragma unroll
        for (int c = 0; c < 4; c++) s2[t][c] = pk(lo[c], hi[c]);
    }
    // M[g][k][m] = sum_{l,v} act_W[k][2r+l] * head_W[r*2+l][v] * body_W[(r*2+j)*4+v][m], g=2r+j
    if (t < 108) {
        int gp = t / 18, km = t % 18;
        int k = km / 2, m = km % 2;
        float val[2];
        #pragma unroll
        for (int h = 0; h < 2; h++) {
            int g = 2*gp + h;
            int r = g / 2, j = g % 2;
            float s = 0.0f;
            #pragma unroll
            for (int l = 0; l < 2; l++) {
                float aw = act_W[k*12 + 2*r + l];
                #pragma unroll
                for (int v = 0; v < 4; v++)
                    s += aw * a_head_W[(r*2+l)*4 + v] * a_body_W[((r*2+j)*4 + v)*2 + m];
            }
            val[h] = s;
        }
        sMp[gp][km] = pk(val[0], val[1]);
    }
    if (t < 9) {
        float s = act_b[t];
        #pragma unroll
        for (int m12 = 0; m12 < 12; m12++) {
            int r = m12 / 2;
            float cb = a_head_b[m12];
            #pragma unroll
            for (int v = 0; v < 4; v++)
                cb += a_head_W[m12*4 + v] * (a_body_b[(r*2+0)*4 + v] + a_body_b[(r*2+1)*4 + v]);
            s += act_W[t*12 + m12] * cb;
        }
        s_qb[t] = s;
    }

    // ---- coalesced input staging ----
    const long long in_base = (long long)blockIdx.x * (BLK * 18);
    const long long in_lim  = (long long)B * 18;
    #pragma unroll
    for (int k = t; k < BLK * 18; k += BLK) {
        long long g = in_base + k;
        s_io[(k/18)*19 + (k%18)] = (g < in_lim) ? state[g] : 0.0f;
    }
    __syncthreads();

    // ---- per-row load + squares ----
    float x[9], y[9], x2[9], y2[9];
    {
        const float* my = &s_io[t * 19];
        #pragma unroll
        for (int i = 0; i < 9; i++) {
            x[i] = my[2*i]; y[i] = my[2*i+1];
            x2[i] = x[i]*x[i]; y2[i] = y[i]*y[i];
        }
    }

    // ---- ConcreteLayer (scalar): cf features stored pre-duplicated as pairs ----
    u64 cf0d[12], cf1d[12];
    #pragma unroll
    for (int r = 0; r < 12; r++) {
        const float4 a = s1a[r];
        const float n1 = s1b[r];
        float sum = 0.0f, wsum = 0.0f, em = 0.0f;
        #pragma unroll
        for (int i = 0; i < 9; i++) {
            float m = fmaf(a.y, x[i], a.x);
            m = fmaf(a.z, x2[i], m);
            m = fmaf(a.w, y[i], m);
            m = fmaf(n1, y2[i], m);          // m = -ms * log2e
            float e = ex2f(m);
            em = fmaxf(em, e);
            sum += e;
            wsum = fmaf(e, y[i], wsum);
        }
        float c1 = wsum * rcpf(sum);
        cf0d[r] = pk(em, em);                // exp(-min ms) = max e
        cf1d[r] = pk(c1, c1);
    }

    // ---- q accumulators: even-g contributions in lo, odd-g in hi ----
    u64 qp[9];
    #pragma unroll
    for (int k = 0; k < 9; k++) qp[k] = pk(s_qb[k], 0.0f);

    // ---- AbstractionLayer: 6 group-pairs, packed f32x2 ----
    #pragma unroll
    for (int gp = 0; gp < 6; gp++) {
        const u64 nta0 = s2[gp][0], n0 = s2[gp][1], nta1 = s2[gp][2], n1 = s2[gp][3];
        u64 sum = 0ull, s0 = 0ull, s1 = 0ull;
        #pragma unroll
        for (int i = 0; i < 12; i++) {
            u64 d0 = f2add(cf0d[i], nta0);
            u64 d1 = f2add(cf1d[i], nta1);
            u64 m  = f2mul(f2mul(n0, d0), d0);
            m = f2fma(f2mul(n1, d1), d1, m);     // m = -ms*log2e, both groups
            float mlo, mhi; unpk(m, mlo, mhi);
            u64 e = pk(ex2f(mlo), ex2f(mhi));
            sum = f2add(sum, e);
            s0  = f2fma(e, cf0d[i], s0);
            s1  = f2fma(e, cf1d[i], s1);
        }
        float slo, shi; unpk(sum, slo, shi);
        u64 inv  = pk(rcpf(slo), rcpf(shi));
        u64 sel0 = f2mul(s0, inv);
        u64 sel1 = f2mul(s1, inv);
        const u64* M = sMp[gp];
        #pragma unroll
        for (int k = 0; k < 9; k++) {
            qp[k] = f2fma(M[k*2 + 0], sel0, qp[k]);
            qp[k] = f2fma(M[k*2 + 1], sel1, qp[k]);
        }
    }

    // ---- horizontal add + output staging + coalesced store ----
    __syncthreads();
    #pragma unroll
    for (int k = 0; k < 9; k++) {
        float lo, hi; unpk(qp[k], lo, hi);
        s_io[t*9 + k] = lo + hi;
    }
    __syncthreads();

    const long long out_base = (long long)blockIdx.x * (BLK * 9);
    const long long out_lim  = (long long)B * 9;
    #pragma unroll
    for (int k = t; k < BLK * 9; k += BLK) {
        long long g = out_base + k;
        if (g < out_lim) out[g] = s_io[k];
    }
}

extern "C" void kernel_launch(void* const* d_in, const int* in_sizes, int n_in,
                              void* d_out, int out_size) {
    const float* state       = (const float*)d_in[0];
    const float* c_templates = (const float*)d_in[1];
    const float* c_gammas    = (const float*)d_in[2];
    const float* a_templates = (const float*)d_in[3];
    const float* a_gammas    = (const float*)d_in[4];
    const float* a_body_W    = (const float*)d_in[5];
    const float* a_body_b    = (const float*)d_in[6];
    const float* a_head_W    = (const float*)d_in[7];
    const float* a_head_b    = (const float*)d_in[8];
    const float* act_W       = (const float*)d_in[9];
    const float* act_b       = (const float*)d_in[10];
    float* out = (float*)d_out;

    const int B = in_sizes[0] / 18;
    const int grid = (B + BLK - 1) / BLK;
    logic_kernel<<<grid, BLK>>>(state, c_templates, c_gammas, a_templates,
                                a_gammas, a_body_W, a_body_b, a_head_W,
                                a_head_b, act_W, act_b, out, B);
}

// round 7
// speedup vs baseline: 1.2505x; 1.0820x over previous
#include <cuda_runtime.h>

#define LOG2E 1.4426950408889634f
#define BLK 128

typedef unsigned long long u64;

__device__ __forceinline__ float ex2f(float x){ float y; asm("ex2.approx.f32 %0, %1;" : "=f"(y) : "f"(x)); return y; }
__device__ __forceinline__ float rcpf(float x){ float y; asm("rcp.approx.f32 %0, %1;" : "=f"(y) : "f"(x)); return y; }
__device__ __forceinline__ u64 pk(float lo, float hi){ u64 r; asm("mov.b64 %0, {%1,%2};" : "=l"(r) : "f"(lo), "f"(hi)); return r; }
__device__ __forceinline__ void unpk(u64 v, float& lo, float& hi){ asm("mov.b64 {%0,%1}, %2;" : "=f"(lo), "=f"(hi) : "l"(v)); }
__device__ __forceinline__ u64 f2fma(u64 a,u64 b,u64 c){ u64 d; asm("fma.rn.f32x2 %0, %1, %2, %3;" : "=l"(d) : "l"(a),"l"(b),"l"(c)); return d; }
__device__ __forceinline__ u64 f2add(u64 a,u64 b){ u64 d; asm("add.rn.f32x2 %0, %1, %2;" : "=l"(d) : "l"(a),"l"(b)); return d; }
__device__ __forceinline__ u64 f2mul(u64 a,u64 b){ u64 d; asm("mul.rn.f32x2 %0, %1, %2;" : "=l"(d) : "l"(a),"l"(b)); return d; }

__global__ __launch_bounds__(BLK, 6)
void logic_kernel(const float* __restrict__ state,
                  const float* __restrict__ c_templates,
                  const float* __restrict__ c_gammas,
                  const float* __restrict__ a_templates,
                  const float* __restrict__ a_gammas,
                  const float* __restrict__ a_body_W,
                  const float* __restrict__ a_body_b,
                  const float* __restrict__ a_head_W,
                  const float* __restrict__ a_head_b,
                  const float* __restrict__ act_W,
                  const float* __restrict__ act_b,
                  float* __restrict__ out, int B)
{
    // Layer-1 per rule, Horner form (log2 dom): m = C + x*(u0 + n0*x) + y*(u1 + n1*y)
    __shared__ float4 s1a[12];   // {C, u0, n0, u1}
    __shared__ float  s1b[12];   // n1
    // Layer-2 per group-PAIR, packed {g=2p | g=2p+1}, same Horner form over (cf0, cf1)
    __shared__ u64 s2[6][5];     // {C, u0, n0, u1, n1}
    // Collapsed tail: q += M[g] @ sel; M packed across the group pair
    __shared__ u64 sMp[6][18];   // [gpair][k*2+m] = {M[2p][k][m] | M[2p+1][k][m]}
    __shared__ float s_qb[9];
    __shared__ float s_io[BLK * 19];   // input staging; reused as output staging

    const int t = threadIdx.x;

    if (t < 12) {
        float t0 = c_templates[2*t], t1 = c_templates[2*t+1];
        float w0 = (1.0f - __saturatef(c_gammas[2*t]))   * LOG2E;
        float w1 = (1.0f - __saturatef(c_gammas[2*t+1])) * LOG2E;
        float4 a;
        a.x = -(w0*t0*t0 + w1*t1*t1);   // C
        a.y = 2.0f*w0*t0;               // u0
        a.z = -w0;                      // n0
        a.w = 2.0f*w1*t1;               // u1
        s1a[t] = a;
        s1b[t] = -w1;                   // n1
    }
    if (t < 6) {
        float lo[5], hi[5];
        #pragma unroll
        for (int h = 0; h < 2; h++) {
            int g = 2*t + h;
            float a0 = a_templates[2*g], a1 = a_templates[2*g+1];
            float v0 = (1.0f - __saturatef(a_gammas[2*g]))   * LOG2E;
            float v1 = (1.0f - __saturatef(a_gammas[2*g+1])) * LOG2E;
            float* d = h ? hi : lo;
            d[0] = -(v0*a0*a0 + v1*a1*a1);  // C
            d[1] = 2.0f*v0*a0;              // u0
            d[2] = -v0;                     // n0
            d[3] = 2.0f*v1*a1;              // u1
            d[4] = -v1;                     // n1
        }
        #pragma unroll
        for (int c = 0; c < 5; c++) s2[t][c] = pk(lo[c], hi[c]);
    }
    // M[g][k][m] = sum_{l,v} act_W[k][2r+l] * head_W[r*2+l][v] * body_W[(r*2+j)*4+v][m], g=2r+j
    if (t < 108) {
        int gp = t / 18, km = t % 18;
        int k = km / 2, m = km % 2;
        float val[2];
        #pragma unroll
        for (int h = 0; h < 2; h++) {
            int g = 2*gp + h;
            int r = g / 2, j = g % 2;
            float s = 0.0f;
            #pragma unroll
            for (int l = 0; l < 2; l++) {
                float aw = act_W[k*12 + 2*r + l];
                #pragma unroll
                for (int v = 0; v < 4; v++)
                    s += aw * a_head_W[(r*2+l)*4 + v] * a_body_W[((r*2+j)*4 + v)*2 + m];
            }
            val[h] = s;
        }
        sMp[gp][km] = pk(val[0], val[1]);
    }
    if (t < 9) {
        float s = act_b[t];
        #pragma unroll
        for (int m12 = 0; m12 < 12; m12++) {
            int r = m12 / 2;
            float cb = a_head_b[m12];
            #pragma unroll
            for (int v = 0; v < 4; v++)
                cb += a_head_W[m12*4 + v] * (a_body_b[(r*2+0)*4 + v] + a_body_b[(r*2+1)*4 + v]);
            s += act_W[t*12 + m12] * cb;
        }
        s_qb[t] = s;
    }

    // ---- coalesced input staging ----
    const long long in_base = (long long)blockIdx.x * (BLK * 18);
    const long long in_lim  = (long long)B * 18;
    #pragma unroll
    for (int k = t; k < BLK * 18; k += BLK) {
        long long g = in_base + k;
        s_io[(k/18)*19 + (k%18)] = (g < in_lim) ? state[g] : 0.0f;
    }
    __syncthreads();

    // ---- per-row load (no square precompute — Horner form) ----
    float x[9], y[9];
    {
        const float* my = &s_io[t * 19];
        #pragma unroll
        for (int i = 0; i < 9; i++) { x[i] = my[2*i]; y[i] = my[2*i+1]; }
    }

    // ---- ConcreteLayer (scalar, Horner, max over m) ----
    u64 cf0d[12], cf1d[12];
    #pragma unroll
    for (int r = 0; r < 12; r++) {
        const float4 a = s1a[r];
        const float n1 = s1b[r];
        float sum = 0.0f, wsum = 0.0f, mn = -3.4e38f;
        #pragma unroll
        for (int i = 0; i < 9; i++) {
            float tx = fmaf(a.z, x[i], a.y);     // u0 + n0*x
            float m  = fmaf(tx, x[i], a.x);      // C + x*(...)
            float ty = fmaf(n1, y[i], a.w);      // u1 + n1*y
            m = fmaf(ty, y[i], m);               // m = -ms*log2e
            mn = fmaxf(mn, m);                   // max m  <=>  min ms
            float e = ex2f(m);
            sum += e;
            wsum = fmaf(e, y[i], wsum);
        }
        float c0 = ex2f(mn);                     // exp(-min ms)
        float c1 = wsum * rcpf(sum);
        cf0d[r] = pk(c0, c0);
        cf1d[r] = pk(c1, c1);
    }

    // ---- q accumulators: even-g in lo, odd-g in hi ----
    u64 qp[9];
    #pragma unroll
    for (int k = 0; k < 9; k++) qp[k] = pk(s_qb[k], 0.0f);

    // ---- AbstractionLayer: 6 group-pairs, packed f32x2, Horner ----
    #pragma unroll
    for (int gp = 0; gp < 6; gp++) {
        const u64 Cd = s2[gp][0], u0d = s2[gp][1], n0d = s2[gp][2];
        const u64 u1d = s2[gp][3], n1d = s2[gp][4];
        u64 sum = 0ull, s0 = 0ull, s1 = 0ull;
        #pragma unroll
        for (int i = 0; i < 12; i++) {
            u64 t0 = f2fma(n0d, cf0d[i], u0d);
            u64 m  = f2fma(t0,  cf0d[i], Cd);
            u64 t1 = f2fma(n1d, cf1d[i], u1d);
            m = f2fma(t1, cf1d[i], m);           // m = -ms*log2e, both groups
            float mlo, mhi; unpk(m, mlo, mhi);
            u64 e = pk(ex2f(mlo), ex2f(mhi));
            sum = f2add(sum, e);
            s0  = f2fma(e, cf0d[i], s0);
            s1  = f2fma(e, cf1d[i], s1);
        }
        float slo, shi; unpk(sum, slo, shi);
        u64 inv  = pk(rcpf(slo), rcpf(shi));
        u64 sel0 = f2mul(s0, inv);
        u64 sel1 = f2mul(s1, inv);
        const u64* M = sMp[gp];
        #pragma unroll
        for (int k = 0; k < 9; k++) {
            qp[k] = f2fma(M[k*2 + 0], sel0, qp[k]);
            qp[k] = f2fma(M[k*2 + 1], sel1, qp[k]);
        }
    }

    // ---- horizontal add + output staging + coalesced store ----
    __syncthreads();
    #pragma unroll
    for (int k = 0; k < 9; k++) {
        float lo, hi; unpk(qp[k], lo, hi);
        s_io[t*9 + k] = lo + hi;
    }
    __syncthreads();

    const long long out_base = (long long)blockIdx.x * (BLK * 9);
    const long long out_lim  = (long long)B * 9;
    #pragma unroll
    for (int k = t; k < BLK * 9; k += BLK) {
        long long g = out_base + k;
        if (g < out_lim) out[g] = s_io[k];
    }
}

extern "C" void kernel_launch(void* const* d_in, const int* in_sizes, int n_in,
                              void* d_out, int out_size) {
    const float* state       = (const float*)d_in[0];
    const float* c_templates = (const float*)d_in[1];
    const float* c_gammas    = (const float*)d_in[2];
    const float* a_templates = (const float*)d_in[3];
    const float* a_gammas    = (const float*)d_in[4];
    const float* a_body_W    = (const float*)d_in[5];
    const float* a_body_b    = (const float*)d_in[6];
    const float* a_head_W    = (const float*)d_in[7];
    const float* a_head_b    = (const float*)d_in[8];
    const float* act_W       = (const float*)d_in[9];
    const float* act_b       = (const float*)d_in[10];
    float* out = (float*)d_out;

    const int B = in_sizes[0] / 18;
    const int grid = (B + BLK - 1) / BLK;
    logic_kernel<<<grid, BLK>>>(state, c_templates, c_gammas, a_templates,
                                a_gammas, a_body_W, a_body_b, a_head_W,
                                a_head_b, act_W, act_b, out, B);
}